// round 10
// baseline (speedup 1.0000x reference)
#include <cuda_runtime.h>
#include <cuda_bf16.h>
#include <math.h>
#include <stdint.h>

constexpr int B_ = 4, H_ = 144, W_ = 144;
constexpr int HW_ = H_ * W_;        // 20736
constexpr int NT  = B_ * HW_;       // 82944 = 648*128
constexpr int HO = 142, WO = 142, HWO = HO * WO, NH = B_ * HWO;
constexpr int PXT = NT / 128;       // 648
constexpr int SE = 1920, KR = 320;

// ---------- scratch ----------
__device__ float         g_E [ (size_t)NT * SE ];
__device__ float         g_c12f[(size_t)NT * KR];
__device__ float         g_ct1f[(size_t)NT * KR];
__device__ float         g_xt1f[(size_t)NT * KR];
__device__ __nv_bfloat16 g_x12h[(size_t)(NT+512) * KR], g_x12l[(size_t)(NT+512) * KR];
__device__ __nv_bfloat16 g_xt1h[(size_t)(NT+512) * KR], g_xt1l[(size_t)(NT+512) * KR];
__device__ __nv_bfloat16 g_Yxh[(size_t)NT * 64], g_Yxl[(size_t)NT * 64];
__device__ __nv_bfloat16 g_H1h[(size_t)NT * 128], g_H1l[(size_t)NT * 128];
__device__ float         g_H2 [(size_t)NT * 128];
__device__ __nv_bfloat16 g_Wench[1920 * 64], g_Wencl[1920 * 64];
__device__ __nv_bfloat16 g_W2h[1280 * 320], g_W2l[1280 * 320];
__device__ __nv_bfloat16 g_W1h[1280 * 320], g_W1l[1280 * 320];
__device__ __nv_bfloat16 g_L1h[9 * 128 * 320], g_L1l[9 * 128 * 320];
__device__ __nv_bfloat16 g_L2h[128 * 128], g_L2l[128 * 128];
__device__ float g_benc[1920], g_b2[1280], g_b1[1280];

// ---------- helpers ----------
__device__ __forceinline__ uint32_t s2u(const void* p) {
    uint32_t a;
    asm("{ .reg .u64 t; cvta.to.shared.u64 t, %1; cvt.u32.u64 %0, t; }" : "=r"(a) : "l"(p));
    return a;
}
__device__ __forceinline__ float gelu_f(float x) {
    return 0.5f * x * (1.0f + erff(x * 0.70710678118654752440f));
}
__device__ __forceinline__ float sigm_f(float x) { return 1.0f / (1.0f + expf(-x)); }
__device__ __forceinline__ void splitb(float x, __nv_bfloat16& h, __nv_bfloat16& l) {
    h = __float2bfloat16(x);
    l = __float2bfloat16(x - __bfloat162float(h));
}
__device__ __forceinline__ void ldmx4(uint32_t* r, uint32_t addr) {
    asm volatile("ldmatrix.sync.aligned.m8n8.x4.shared.b16 {%0,%1,%2,%3}, [%4];"
                 : "=r"(r[0]), "=r"(r[1]), "=r"(r[2]), "=r"(r[3]) : "r"(addr));
}
__device__ __forceinline__ void hmma(float* c, const uint32_t* a, uint32_t b0, uint32_t b1) {
    asm volatile("mma.sync.aligned.m16n8k16.row.col.f32.bf16.bf16.f32 "
                 "{%0,%1,%2,%3}, {%4,%5,%6,%7}, {%8,%9}, {%0,%1,%2,%3};"
                 : "+f"(c[0]), "+f"(c[1]), "+f"(c[2]), "+f"(c[3])
                 : "r"(a[0]), "r"(a[1]), "r"(a[2]), "r"(a[3]), "r"(b0), "r"(b1));
}

// ================= generic tiled MMA GEMM (bf16x3, mma.sync) =================
// MODE 0: outf = gelu(D+bias)     MODE 1: outh/outl = split(gelu(D+bias))
// MODE 2: fused LSTM gate epilogue; STEP 0 = gate'2' (A-step), STEP 1 = gate'1' (B-step).
//         Gate state referenced via __device__ globals (no extra live params in mainloop).
template<int MODE, int STEP>
__global__ void __launch_bounds__(512, 1)
mma_gemm(const __nv_bfloat16* __restrict__ Ah, const __nv_bfloat16* __restrict__ Al,
         const __nv_bfloat16* __restrict__ Bh, const __nv_bfloat16* __restrict__ Bl,
         const float* __restrict__ bias,
         float* __restrict__ outf, __nv_bfloat16* __restrict__ outh, __nv_bfloat16* __restrict__ outl,
         int kpad, int nchunks, int ntaps, int conv, int ostride)
{
    extern __shared__ char smem[];
    const uint32_t sb = s2u(smem);
    const int tid = threadIdx.x;
    const int lane = tid & 31, warp = tid >> 5;
    const int wm = warp >> 2, wn = warp & 3;
    const int ch0 = blockIdx.x * 128;
    const int n0  = blockIdx.y * 128;

    const int ldRow = tid >> 2, ldC = tid & 3;

    const uint32_t aOff = (uint32_t)((wm * 32 + (lane & 15)) * 80 + (lane >> 4) * 16);
    const uint32_t bOff = (uint32_t)((wn * 32 + ((lane >> 4) & 1) * 8 + (lane & 7)) * 80
                                     + ((lane >> 3) & 1) * 16);

    float acc[2][4][4];
#pragma unroll
    for (int i = 0; i < 2; i++)
#pragma unroll
        for (int j = 0; j < 4; j++)
#pragma unroll
            for (int q = 0; q < 4; q++) acc[i][j][q] = 0.f;

    const int total = ntaps * nchunks;

    {   // prologue: chunk 0 -> stage 0
        long long ao = (long long)(n0 + ldRow) * kpad + ldC * 8;
        long long bo = (long long)(ch0 + ldRow) * kpad + ldC * 8;
        char* st = smem + ldRow * 80 + ldC * 16;
        *(uint4*)(st        ) = *(const uint4*)(Ah + ao);
        *(uint4*)(st + 10240) = *(const uint4*)(Al + ao);
        *(uint4*)(st + 20480) = *(const uint4*)(Bh + bo);
        *(uint4*)(st + 30720) = *(const uint4*)(Bl + bo);
    }
    __syncthreads();

    for (int tc = 0; tc < total; tc++) {
        const int stage = tc & 1;
        uint4 pf[4];
        const bool more = (tc + 1) < total;
        if (more) {
            int t1 = tc + 1;
            int tap = t1 / nchunks, chunk = t1 - tap * nchunks;
            int tapOff = conv ? ((tap / 3) * 144 + (tap % 3)) : 0;
            int brow0  = conv ? tap * 128 : 0;
            long long k0 = (long long)chunk * 32;
            long long ao = (long long)(n0 + ldRow + tapOff) * kpad + k0 + ldC * 8;
            long long bo = (long long)(brow0 + ch0 + ldRow) * kpad + k0 + ldC * 8;
            pf[0] = *(const uint4*)(Ah + ao);
            pf[1] = *(const uint4*)(Al + ao);
            pf[2] = *(const uint4*)(Bh + bo);
            pf[3] = *(const uint4*)(Bl + bo);
        }

        const uint32_t sbase = sb + stage * 40960;
#pragma unroll
        for (int kb = 0; kb < 2; kb++) {
            uint32_t ah[2][4], al[2][4], bh[2][4], bl[2][4];
#pragma unroll
            for (int mt = 0; mt < 2; mt++) {
                uint32_t ad = sbase + kb * 32 + mt * 1280 + aOff;
                ldmx4(ah[mt], ad);
                ldmx4(al[mt], ad + 10240);
            }
#pragma unroll
            for (int np = 0; np < 2; np++) {
                uint32_t bd = sbase + 20480 + kb * 32 + np * 1280 + bOff;
                ldmx4(bh[np], bd);
                ldmx4(bl[np], bd + 10240);
            }
#pragma unroll
            for (int mt = 0; mt < 2; mt++)
#pragma unroll
                for (int nt = 0; nt < 4; nt++) {
                    const int np = nt >> 1, q = (nt & 1) * 2;
                    hmma(acc[mt][nt], ah[mt], bh[np][q], bh[np][q + 1]);
                    hmma(acc[mt][nt], ah[mt], bl[np][q], bl[np][q + 1]);
                    hmma(acc[mt][nt], al[mt], bh[np][q], bh[np][q + 1]);
                }
        }

        if (more) {
            char* st = smem + (stage ^ 1) * 40960 + ldRow * 80 + ldC * 16;
            *(uint4*)(st        ) = pf[0];
            *(uint4*)(st + 10240) = pf[1];
            *(uint4*)(st + 20480) = pf[2];
            *(uint4*)(st + 30720) = pf[3];
            __syncthreads();
        }
    }

    if (MODE == 2) {
        // ---- fused gate epilogue: stage gelu(D+bias) in smem, then gate math ----
        // Gate state via global symbols (compile-time): no regs live through mainloop.
        constexpr int e_a = (STEP == 0) ? 300 : 0;
        constexpr int e_f = (STEP == 0) ? 1200 : 600;
        constexpr int e_i = (STEP == 0) ? 1500 : 900;
        __syncthreads();
        float* Gs = (float*)smem;      // 128 rows x pitch 132 floats
        const int rb = wm * 32 + (lane >> 2);
        const int cb = wn * 32 + (lane & 3) * 2;
#pragma unroll
        for (int mt = 0; mt < 2; mt++)
#pragma unroll
            for (int nt = 0; nt < 4; nt++) {
                const int col = cb + nt * 8;
                const float b0 = bias[ch0 + col], b1 = bias[ch0 + col + 1];
#pragma unroll
                for (int half = 0; half < 2; half++) {
                    const int row = rb + mt * 16 + half * 8;
                    float2 v;
                    v.x = gelu_f(acc[mt][nt][half * 2 + 0] + b0);
                    v.y = gelu_f(acc[mt][nt][half * 2 + 1] + b1);
                    *(float2*)&Gs[row * 132 + col] = v;
                }
            }
        __syncthreads();

        const int cg = tid & 31;             // channel within tile
        const int rch = (ch0 >> 2) + cg;     // global channel
        if (rch < 300) {
#pragma unroll
            for (int p = 0; p < 8; p++) {
                const int row = p * 16 + (tid >> 5);
                float4 g = *(const float4*)&Gs[row * 132 + cg * 4];  // gd,gf,gi,pad
                const long long n = n0 + row;
                const float* Er = g_E + n * SE;
                float f = sigm_f(g.y + Er[e_f + rch]);
                float t = sigm_f(g.z + Er[e_i + rch]);
                size_t o = (size_t)n * KR + rch;
                float ctl = Er[e_a + rch] + g_xt1f[o] - g.x;
                float cin = (STEP == 0) ? g_c12f[o] : g_ct1f[o];
                float c = cin * f + ctl * t;
                if (STEP == 0) g_ct1f[o] = c; else g_c12f[o] = c;
                float x = fmaxf(c, 0.f);
                __nv_bfloat16 hh, ll; splitb(x, hh, ll);
                if (STEP == 0) {
                    g_xt1f[o] = x;
                    g_xt1h[o] = hh; g_xt1l[o] = ll;
                } else {
                    g_x12h[o] = hh; g_x12l[o] = ll;
                }
            }
        }
        return;
    }

    // ---- modes 0/1: direct fragment epilogue ----
    const int rbase = n0 + wm * 32 + (lane >> 2);
    const int cbase = ch0 + wn * 32 + (lane & 3) * 2;
#pragma unroll
    for (int mt = 0; mt < 2; mt++)
#pragma unroll
        for (int nt = 0; nt < 4; nt++) {
            const int col = cbase + nt * 8;
            const float b0 = bias[col], b1 = bias[col + 1];
#pragma unroll
            for (int half = 0; half < 2; half++) {
                const long long row = rbase + mt * 16 + half * 8;
                float v0 = gelu_f(acc[mt][nt][half * 2 + 0] + b0);
                float v1 = gelu_f(acc[mt][nt][half * 2 + 1] + b1);
                if (MODE == 0) {
                    *(float2*)(outf + row * ostride + col) = make_float2(v0, v1);
                } else {
                    __nv_bfloat16 h0, l0, h1, l1;
                    splitb(v0, h0, l0);
                    splitb(v1, h1, l1);
                    uint32_t ph = (uint32_t)__bfloat16_as_ushort(h0) |
                                  ((uint32_t)__bfloat16_as_ushort(h1) << 16);
                    uint32_t pl = (uint32_t)__bfloat16_as_ushort(l0) |
                                  ((uint32_t)__bfloat16_as_ushort(l1) << 16);
                    *(uint32_t*)(outh + row * ostride + col) = ph;
                    *(uint32_t*)(outl + row * ostride + col) = pl;
                }
            }
        }
}

// ---------- packs ----------
__global__ void pack_encN(const float* w0, const float* w1, const float* w2,
                          const float* w3, const float* w4, const float* w5,
                          const float* b0, const float* b1, const float* b2,
                          const float* b3, const float* b4, const float* b5)
{
    int idx = blockIdx.x * blockDim.x + threadIdx.x;
    if (idx >= 1920 * 64) return;
    const float* ws[6] = {w0, w1, w2, w3, w4, w5};
    const float* bs[6] = {b0, b1, b2, b3, b4, b5};
    int r0 = idx / 64, k = idx % 64;
    float v = 0.f;
    if (r0 < 1800 && k < 21) { int s = r0 / 300, r = r0 % 300; v = ws[s][r * 21 + k]; }
    __nv_bfloat16 h, l; splitb(v, h, l);
    g_Wench[idx] = h; g_Wencl[idx] = l;
    if (k == 0) {
        float b = 0.f;
        if (r0 < 1800) { int s = r0 / 300, r = r0 % 300; b = bs[s][r]; }
        g_benc[r0] = b;
    }
}

// channel-interleaved: row 4r+{0,1,2} = wd/wf/wi[r], 4r+3 = 0
__global__ void pack_recI(const float* wd, const float* wf, const float* wi,
                          const float* bd, const float* bf, const float* bi,
                          __nv_bfloat16* Wh, __nv_bfloat16* Wl, float* bout)
{
    int idx = blockIdx.x * blockDim.x + threadIdx.x;
    if (idx >= 1280 * 320) return;
    int r0 = idx / 320, k = idx % 320;
    int cg = r0 >> 2, gg = r0 & 3;
    float v = 0.f;
    if (gg < 3 && cg < 300 && k < 300)
        v = ((gg == 0) ? wd : (gg == 1) ? wf : wi)[cg * 300 + k];
    __nv_bfloat16 h, l; splitb(v, h, l);
    Wh[idx] = h; Wl[idx] = l;
    if (k == 0) {
        float b = 0.f;
        if (gg < 3 && cg < 300) b = ((gg == 0) ? bd : (gg == 1) ? bf : bi)[cg];
        bout[r0] = b;
    }
}

__global__ void pack_l1N(const float* __restrict__ w)
{
    int idx = blockIdx.x * blockDim.x + threadIdx.x;
    if (idx >= 9 * 128 * 320) return;
    int tap = idx / (128 * 320), rem = idx % (128 * 320);
    int ch = rem / 320, k = rem % 320;
    float v = (k < 300) ? w[ch * 2700 + k * 9 + tap] : 0.f;
    __nv_bfloat16 h, l; splitb(v, h, l);
    g_L1h[idx] = h; g_L1l[idx] = l;
}

__global__ void pack_l2N(const float* __restrict__ w)
{
    int idx = blockIdx.x * blockDim.x + threadIdx.x;
    if (idx >= 128 * 128) return;
    __nv_bfloat16 h, l; splitb(w[idx], h, l);
    g_L2h[idx] = h; g_L2l[idx] = l;
}

__global__ void repack_yN(const float* __restrict__ y)
{
    int idx = blockIdx.x * blockDim.x + threadIdx.x;
    if (idx >= NT * 64) return;
    int n = idx / 64, k = idx % 64;
    float v = 0.f;
    if (k < 21) { int b = n / HW_, p = n % HW_; v = y[(b * 21 + k) * HW_ + p]; }
    __nv_bfloat16 h, l; splitb(v, h, l);
    g_Yxh[idx] = h; g_Yxl[idx] = l;
}

// ---------- init ----------
__global__ void init_ew()
{
    int n = blockIdx.x, r = threadIdx.x;
    if (r >= 300) return;
    size_t o = (size_t)n * KR + r;
    const float* Er = g_E + (size_t)n * SE;
    float c = sigm_f(Er[900 + r]) * (-Er[r]);
    g_c12f[o] = c;
    float x = fmaxf(c, 0.f);
    __nv_bfloat16 h, l; splitb(x, h, l);
    g_x12h[o] = h; g_x12l[o] = l;
    g_xt1f[o] = 0.f;
}

// ---------- final head ----------
__global__ void head_out(const float* __restrict__ w3, const float* __restrict__ b3,
                         float* __restrict__ out)
{
    int n = blockIdx.x * blockDim.x + threadIdx.x;
    if (n >= NH) return;
    int b = n / HWO, q = n % HWO, i = q / WO, j = q % WO;
    const float* row = g_H2 + (size_t)(b * HW_ + i * W_ + j) * 128;
    float s = b3[0];
#pragma unroll
    for (int c = 0; c < 128; c += 4) {
        float4 h = *(const float4*)(row + c);
        float4 w = *(const float4*)(w3 + c);
        s += h.x * w.x + h.y * w.y + h.z * w.z + h.w * w.w;
    }
    out[n] = s;
}

// ---------- launcher ----------
#define GSA(p, s) cudaGetSymbolAddress((void**)&(p), s)

extern "C" void kernel_launch(void* const* d_in, const int* in_sizes, int n_in,
                              void* d_out, int out_size)
{
    (void)in_sizes; (void)n_in; (void)out_size;
    const float* in[31];
    for (int i = 0; i < 31; i++) in[i] = (const float*)d_in[i];

    static bool attr = false;
    if (!attr) {
        cudaFuncSetAttribute(mma_gemm<0,0>, cudaFuncAttributeMaxDynamicSharedMemorySize, 81920);
        cudaFuncSetAttribute(mma_gemm<1,0>, cudaFuncAttributeMaxDynamicSharedMemorySize, 81920);
        cudaFuncSetAttribute(mma_gemm<2,0>, cudaFuncAttributeMaxDynamicSharedMemorySize, 81920);
        cudaFuncSetAttribute(mma_gemm<2,1>, cudaFuncAttributeMaxDynamicSharedMemorySize, 81920);
        attr = true;
    }

    float *E, *H2, *benc, *b2, *b1;
    __nv_bfloat16 *Yxh, *Yxl, *Weh, *Wel, *W2h, *W2l, *W1h, *W1l;
    __nv_bfloat16 *x12h, *x12l, *xt1h, *xt1l, *L1h, *L1l, *L2h, *L2l, *H1h, *H1l;
    GSA(E, g_E); GSA(H2, g_H2);
    GSA(benc, g_benc); GSA(b2, g_b2); GSA(b1, g_b1);
    GSA(Yxh, g_Yxh); GSA(Yxl, g_Yxl);
    GSA(Weh, g_Wench); GSA(Wel, g_Wencl);
    GSA(W2h, g_W2h); GSA(W2l, g_W2l); GSA(W1h, g_W1h); GSA(W1l, g_W1l);
    GSA(x12h, g_x12h); GSA(x12l, g_x12l); GSA(xt1h, g_xt1h); GSA(xt1l, g_xt1l);
    GSA(L1h, g_L1h); GSA(L1l, g_L1l); GSA(L2h, g_L2h); GSA(L2l, g_L2l);
    GSA(H1h, g_H1h); GSA(H1l, g_H1l);

    pack_encN<<<(1920 * 64 + 255) / 256, 256>>>(in[1], in[3], in[5], in[7], in[9], in[11],
                                                in[2], in[4], in[6], in[8], in[10], in[12]);
    pack_recI<<<(1280 * 320 + 255) / 256, 256>>>(in[15], in[21], in[23], in[16], in[22], in[24], W2h, W2l, b2);
    pack_recI<<<(1280 * 320 + 255) / 256, 256>>>(in[13], in[17], in[19], in[14], in[18], in[20], W1h, W1l, b1);
    pack_l1N<<<(9 * 128 * 320 + 255) / 256, 256>>>(in[25]);
    pack_l2N<<<(128 * 128 + 255) / 256, 256>>>(in[27]);
    repack_yN<<<(NT * 64 + 255) / 256, 256>>>(in[0]);

    const int SM = 81920;
    // encoders: E = gelu(Wenc @ Yx + benc)
    mma_gemm<0,0><<<dim3(15, PXT), 512, SM>>>(Yxh, Yxl, Weh, Wel, benc, E, 0, 0, 64, 2, 1, 0, SE);
    init_ew<<<NT, 320>>>();

    // gates: STEP0 = gate'2' (E offs 300/1200/1500), STEP1 = gate'1' (0/600/900)
    for (int it = 0; it < 3; it++) {
        mma_gemm<2,0><<<dim3(10, PXT), 512, SM>>>(x12h, x12l, W2h, W2l, b2, 0, 0, 0, KR, 10, 1, 0, 0);
        mma_gemm<2,1><<<dim3(10, PXT), 512, SM>>>(xt1h, xt1l, W1h, W1l, b1, 0, 0, 0, KR, 10, 1, 0, 0);
    }
    mma_gemm<2,0><<<dim3(10, PXT), 512, SM>>>(x12h, x12l, W2h, W2l, b2, 0, 0, 0, KR, 10, 1, 0, 0);

    // head: 3x3 conv as 9 shifted tap-GEMMs, then 1x1, then dot
    mma_gemm<1,0><<<dim3(1, PXT), 512, SM>>>(xt1h, xt1l, L1h, L1l, in[26], 0, H1h, H1l, KR, 10, 9, 1, 128);
    mma_gemm<0,0><<<dim3(1, PXT), 512, SM>>>(H1h, H1l, L2h, L2l, in[28], H2, 0, 0, 128, 4, 1, 0, 128);
    head_out<<<(NH + 255) / 256, 256>>>(in[29], in[30], (float*)d_out);
}

// round 13
// speedup vs baseline: 1.5994x; 1.5994x over previous
#include <cuda_runtime.h>
#include <cuda_fp16.h>
#include <math.h>
#include <stdint.h>

constexpr int B_ = 4, H_ = 144, W_ = 144;
constexpr int HW_ = H_ * W_;        // 20736
constexpr int NT  = B_ * HW_;       // 82944 = 648*128
constexpr int HO = 142, WO = 142, HWO = HO * WO, NH = B_ * HWO;
constexpr int PXT = NT / 128;       // 648
constexpr int SE = 1920, SG = 1024, KR = 320;

// ---------- scratch ----------
__device__ float   g_E [ (size_t)NT * SE ];
__device__ float   g_G [ (size_t)NT * SG ];
__device__ float   g_c12f[(size_t)NT * KR];
__device__ float   g_ct1f[(size_t)NT * KR];
__device__ float   g_xt1f[(size_t)NT * KR];
__device__ __half  g_x12h[(size_t)(NT+512) * KR], g_x12l[(size_t)(NT+512) * KR];
__device__ __half  g_xt1h[(size_t)(NT+512) * KR], g_xt1l[(size_t)(NT+512) * KR];
__device__ __half  g_Yxh[(size_t)NT * 64], g_Yxl[(size_t)NT * 64];
__device__ __half  g_H1h[(size_t)NT * 128], g_H1l[(size_t)NT * 128];
__device__ float   g_H2 [(size_t)NT * 128];
__device__ __half  g_Wench[1920 * 64], g_Wencl[1920 * 64];
__device__ __half  g_W2h[1024 * 320], g_W2l[1024 * 320];
__device__ __half  g_W1h[1024 * 320], g_W1l[1024 * 320];
__device__ __half  g_L1h[9 * 128 * 320], g_L1l[9 * 128 * 320];
__device__ __half  g_L2h[128 * 128], g_L2l[128 * 128];
__device__ float g_benc[1920], g_b2[1024], g_b1[1024];

// ---------- helpers ----------
__device__ __forceinline__ uint32_t s2u(const void* p) {
    uint32_t a;
    asm("{ .reg .u64 t; cvta.to.shared.u64 t, %1; cvt.u32.u64 %0, t; }" : "=r"(a) : "l"(p));
    return a;
}
__device__ __forceinline__ float gelu_f(float x) {
    return 0.5f * x * (1.0f + erff(x * 0.70710678118654752440f));
}
__device__ __forceinline__ float sigm_f(float x) { return 1.0f / (1.0f + expf(-x)); }
__device__ __forceinline__ void splith(float x, __half& h, __half& l) {
    h = __float2half_rn(x);
    l = __float2half_rn(x - __half2float(h));
}
__device__ __forceinline__ void ldmx4(uint32_t* r, uint32_t addr) {
    asm volatile("ldmatrix.sync.aligned.m8n8.x4.shared.b16 {%0,%1,%2,%3}, [%4];"
                 : "=r"(r[0]), "=r"(r[1]), "=r"(r[2]), "=r"(r[3]) : "r"(addr));
}
__device__ __forceinline__ void hmma(float* c, const uint32_t* a, uint32_t b0, uint32_t b1) {
    asm volatile("mma.sync.aligned.m16n8k16.row.col.f32.f16.f16.f32 "
                 "{%0,%1,%2,%3}, {%4,%5,%6,%7}, {%8,%9}, {%0,%1,%2,%3};"
                 : "+f"(c[0]), "+f"(c[1]), "+f"(c[2]), "+f"(c[3])
                 : "r"(a[0]), "r"(a[1]), "r"(a[2]), "r"(a[3]), "r"(b0), "r"(b1));
}

// ================= generic tiled MMA GEMM (fp16 compensated, mma.sync) =================
// MODE 0: outf = gelu(D+bias)  MODE 1: outh/outl = split(gelu(D+bias))
// TERMS: 1 = AhBh; 2 = +AlBh; 3 = +AhBl.
template<int MODE, int TERMS>
__global__ void __launch_bounds__(512, 1)
mma_gemm(const __half* __restrict__ Ah, const __half* __restrict__ Al,
         const __half* __restrict__ Bh, const __half* __restrict__ Bl,
         const float* __restrict__ bias,
         float* __restrict__ outf, __half* __restrict__ outh, __half* __restrict__ outl,
         int kpad, int nchunks, int ntaps, int conv, int ostride, int tile0)
{
    extern __shared__ char smem[];
    const uint32_t sb = s2u(smem);
    const int tid = threadIdx.x;
    const int lane = tid & 31, warp = tid >> 5;
    const int wm = warp >> 2, wn = warp & 3;
    const int ch0 = (blockIdx.x + tile0) * 128;
    const int n0  = blockIdx.y * 128;

    const int ldRow = tid >> 2, ldC = tid & 3;

    const uint32_t aOff = (uint32_t)((wm * 32 + (lane & 15)) * 80 + (lane >> 4) * 16);
    const uint32_t bOff = (uint32_t)((wn * 32 + ((lane >> 4) & 1) * 8 + (lane & 7)) * 80
                                     + ((lane >> 3) & 1) * 16);

    float acc[2][4][4];
#pragma unroll
    for (int i = 0; i < 2; i++)
#pragma unroll
        for (int j = 0; j < 4; j++)
#pragma unroll
            for (int q = 0; q < 4; q++) acc[i][j][q] = 0.f;

    const int total = ntaps * nchunks;

    {   // prologue: chunk 0 -> stage 0
        long long ao = (long long)(n0 + ldRow) * kpad + ldC * 8;
        long long bo = (long long)(ch0 + ldRow) * kpad + ldC * 8;
        char* st = smem + ldRow * 80 + ldC * 16;
        *(uint4*)(st        ) = *(const uint4*)(Ah + ao);
        if (TERMS >= 2) *(uint4*)(st + 10240) = *(const uint4*)(Al + ao);
        *(uint4*)(st + 20480) = *(const uint4*)(Bh + bo);
        if (TERMS >= 3) *(uint4*)(st + 30720) = *(const uint4*)(Bl + bo);
    }
    __syncthreads();

    for (int tc = 0; tc < total; tc++) {
        const int stage = tc & 1;
        uint4 pf[4];
        const bool more = (tc + 1) < total;
        if (more) {
            int t1 = tc + 1;
            int tap = t1 / nchunks, chunk = t1 - tap * nchunks;
            int tapOff = conv ? ((tap / 3) * 144 + (tap % 3)) : 0;
            int brow0  = conv ? tap * 128 : 0;
            long long k0 = (long long)chunk * 32;
            long long ao = (long long)(n0 + ldRow + tapOff) * kpad + k0 + ldC * 8;
            long long bo = (long long)(brow0 + ch0 + ldRow) * kpad + k0 + ldC * 8;
            pf[0] = *(const uint4*)(Ah + ao);
            if (TERMS >= 2) pf[1] = *(const uint4*)(Al + ao);
            pf[2] = *(const uint4*)(Bh + bo);
            if (TERMS >= 3) pf[3] = *(const uint4*)(Bl + bo);
        }

        const uint32_t sbase = sb + stage * 40960;
#pragma unroll
        for (int kb = 0; kb < 2; kb++) {
            uint32_t ah[2][4], al[2][4], bh[2][4], bl[2][4];
#pragma unroll
            for (int mt = 0; mt < 2; mt++) {
                uint32_t ad = sbase + kb * 32 + mt * 1280 + aOff;
                ldmx4(ah[mt], ad);
                if (TERMS >= 2) ldmx4(al[mt], ad + 10240);
            }
#pragma unroll
            for (int np = 0; np < 2; np++) {
                uint32_t bd = sbase + 20480 + kb * 32 + np * 1280 + bOff;
                ldmx4(bh[np], bd);
                if (TERMS >= 3) ldmx4(bl[np], bd + 10240);
            }
#pragma unroll
            for (int mt = 0; mt < 2; mt++)
#pragma unroll
                for (int nt = 0; nt < 4; nt++) {
                    const int np = nt >> 1, q = (nt & 1) * 2;
                    hmma(acc[mt][nt], ah[mt], bh[np][q], bh[np][q + 1]);
                    if (TERMS >= 2) hmma(acc[mt][nt], al[mt], bh[np][q], bh[np][q + 1]);
                    if (TERMS >= 3) hmma(acc[mt][nt], ah[mt], bl[np][q], bl[np][q + 1]);
                }
        }

        if (more) {
            char* st = smem + (stage ^ 1) * 40960 + ldRow * 80 + ldC * 16;
            *(uint4*)(st        ) = pf[0];
            if (TERMS >= 2) *(uint4*)(st + 10240) = pf[1];
            *(uint4*)(st + 20480) = pf[2];
            if (TERMS >= 3) *(uint4*)(st + 30720) = pf[3];
            __syncthreads();
        }
    }

    // ---- epilogue ----
    const int rbase = n0 + wm * 32 + (lane >> 2);
    const int cbase = ch0 + wn * 32 + (lane & 3) * 2;
#pragma unroll
    for (int mt = 0; mt < 2; mt++)
#pragma unroll
        for (int nt = 0; nt < 4; nt++) {
            const int col = cbase + nt * 8;
            const float b0 = bias[col], b1 = bias[col + 1];
#pragma unroll
            for (int half = 0; half < 2; half++) {
                const long long row = rbase + mt * 16 + half * 8;
                float v0 = gelu_f(acc[mt][nt][half * 2 + 0] + b0);
                float v1 = gelu_f(acc[mt][nt][half * 2 + 1] + b1);
                if (MODE == 0) {
                    *(float2*)(outf + row * ostride + col) = make_float2(v0, v1);
                } else {
                    __half h0, l0, h1, l1;
                    splith(v0, h0, l0);
                    splith(v1, h1, l1);
                    uint32_t ph = (uint32_t)__half_as_ushort(h0) |
                                  ((uint32_t)__half_as_ushort(h1) << 16);
                    uint32_t pl = (uint32_t)__half_as_ushort(l0) |
                                  ((uint32_t)__half_as_ushort(l1) << 16);
                    *(uint32_t*)(outh + row * ostride + col) = ph;
                    *(uint32_t*)(outl + row * ostride + col) = pl;
                }
            }
        }
}

// ---------- packs ----------
__global__ void pack_encN(const float* w0, const float* w1, const float* w2,
                          const float* w3, const float* w4, const float* w5,
                          const float* b0, const float* b1, const float* b2,
                          const float* b3, const float* b4, const float* b5)
{
    int idx = blockIdx.x * blockDim.x + threadIdx.x;
    if (idx >= 1920 * 64) return;
    const float* ws[6] = {w0, w1, w2, w3, w4, w5};
    const float* bs[6] = {b0, b1, b2, b3, b4, b5};
    int r0 = idx / 64, k = idx % 64;
    float v = 0.f;
    if (r0 < 1800 && k < 21) { int s = r0 / 300, r = r0 % 300; v = ws[s][r * 21 + k]; }
    __half h, l; splith(v, h, l);
    g_Wench[idx] = h; g_Wencl[idx] = l;
    if (k == 0) {
        float b = 0.f;
        if (r0 < 1800) { int s = r0 / 300, r = r0 % 300; b = bs[s][r]; }
        g_benc[r0] = b;
    }
}

__global__ void pack_recN(const float* wd, const float* wf, const float* wi,
                          const float* bd, const float* bf, const float* bi,
                          __half* Wh, __half* Wl, float* bout)
{
    int idx = blockIdx.x * blockDim.x + threadIdx.x;
    if (idx >= 1024 * 320) return;
    int r0 = idx / 320, k = idx % 320;
    float v = 0.f;
    if (r0 < 900 && k < 300) {
        int g = r0 / 300, r = r0 % 300;
        v = ((g == 0) ? wd : (g == 1) ? wf : wi)[r * 300 + k];
    }
    __half h, l; splith(v, h, l);
    Wh[idx] = h; Wl[idx] = l;
    if (k == 0) {
        float b = 0.f;
        if (r0 < 900) { int g = r0 / 300, r = r0 % 300; b = ((g == 0) ? bd : (g == 1) ? bf : bi)[r]; }
        bout[r0] = b;
    }
}

__global__ void pack_l1N(const float* __restrict__ w)
{
    int idx = blockIdx.x * blockDim.x + threadIdx.x;
    if (idx >= 9 * 128 * 320) return;
    int tap = idx / (128 * 320), rem = idx % (128 * 320);
    int ch = rem / 320, k = rem % 320;
    float v = (k < 300) ? w[ch * 2700 + k * 9 + tap] : 0.f;
    __half h, l; splith(v, h, l);
    g_L1h[idx] = h; g_L1l[idx] = l;
}

__global__ void pack_l2N(const float* __restrict__ w)
{
    int idx = blockIdx.x * blockDim.x + threadIdx.x;
    if (idx >= 128 * 128) return;
    __half h, l; splith(w[idx], h, l);
    g_L2h[idx] = h; g_L2l[idx] = l;
}

__global__ void repack_yN(const float* __restrict__ y)
{
    int idx = blockIdx.x * blockDim.x + threadIdx.x;
    if (idx >= NT * 64) return;
    int n = idx / 64, k = idx % 64;
    float v = 0.f;
    if (k < 21) { int b = n / HW_, p = n % HW_; v = y[(b * 21 + k) * HW_ + p]; }
    __half h, l; splith(v, h, l);
    g_Yxh[idx] = h; g_Yxl[idx] = l;
}

// ---------- elementwise (grid = NT blocks, 320 threads) ----------
__global__ void init_ew()
{
    int n = blockIdx.x, r = threadIdx.x;
    if (r >= 300) return;
    size_t o = (size_t)n * KR + r;
    const float* Er = g_E + (size_t)n * SE;
    float c = sigm_f(Er[900 + r]) * (-Er[r]);
    g_c12f[o] = c;
    float x = fmaxf(c, 0.f);
    __half h, l; splith(x, h, l);
    g_x12h[o] = h; g_x12l[o] = l;
    g_xt1f[o] = 0.f;
}

__global__ void stepA_ew()
{
    int n = blockIdx.x, r = threadIdx.x;
    if (r >= 300) return;
    size_t o = (size_t)n * KR + r;
    const float* Gr = g_G + (size_t)n * SG;
    const float* Er = g_E + (size_t)n * SE;
    float f = sigm_f(Gr[300 + r] + Er[1200 + r]);
    float t = sigm_f(Gr[600 + r] + Er[1500 + r]);
    float ctl = Er[300 + r] + g_xt1f[o] - Gr[r];
    float c = g_c12f[o] * f + ctl * t;
    g_ct1f[o] = c;
    float x = fmaxf(c, 0.f);
    g_xt1f[o] = x;
    __half h, l; splith(x, h, l);
    g_xt1h[o] = h; g_xt1l[o] = l;
}

__global__ void stepB_ew()
{
    int n = blockIdx.x, r = threadIdx.x;
    if (r >= 300) return;
    size_t o = (size_t)n * KR + r;
    const float* Gr = g_G + (size_t)n * SG;
    const float* Er = g_E + (size_t)n * SE;
    float f = sigm_f(Gr[300 + r] + Er[600 + r]);
    float t = sigm_f(Gr[600 + r] + Er[900 + r]);
    float ctl = Er[r] + g_xt1f[o] - Gr[r];
    float c = g_ct1f[o] * f + ctl * t;
    g_c12f[o] = c;
    float x = fmaxf(c, 0.f);
    __half h, l; splith(x, h, l);
    g_x12h[o] = h; g_x12l[o] = l;
}

// ---------- final head ----------
__global__ void head_out(const float* __restrict__ w3, const float* __restrict__ b3,
                         float* __restrict__ out)
{
    int n = blockIdx.x * blockDim.x + threadIdx.x;
    if (n >= NH) return;
    int b = n / HWO, q = n % HWO, i = q / WO, j = q % WO;
    const float* row = g_H2 + (size_t)(b * HW_ + i * W_ + j) * 128;
    float s = b3[0];
#pragma unroll
    for (int c = 0; c < 128; c += 4) {
        float4 h = *(const float4*)(row + c);
        float4 w = *(const float4*)(w3 + c);
        s += h.x * w.x + h.y * w.y + h.z * w.z + h.w * w.w;
    }
    out[n] = s;
}

// ---------- launcher ----------
#define GSA(p, s) cudaGetSymbolAddress((void**)&(p), s)

extern "C" void kernel_launch(void* const* d_in, const int* in_sizes, int n_in,
                              void* d_out, int out_size)
{
    (void)in_sizes; (void)n_in; (void)out_size;
    const float* in[31];
    for (int i = 0; i < 31; i++) in[i] = (const float*)d_in[i];

    static bool attr = false;
    if (!attr) {
        cudaFuncSetAttribute(mma_gemm<0,3>, cudaFuncAttributeMaxDynamicSharedMemorySize, 81920);
        cudaFuncSetAttribute(mma_gemm<0,1>, cudaFuncAttributeMaxDynamicSharedMemorySize, 81920);
        cudaFuncSetAttribute(mma_gemm<1,3>, cudaFuncAttributeMaxDynamicSharedMemorySize, 81920);
        attr = true;
    }

    float *E, *G, *H2, *benc, *b2, *b1;
    __half *Yxh, *Yxl, *Weh, *Wel, *W2h, *W2l, *W1h, *W1l;
    __half *x12h, *x12l, *xt1h, *xt1l, *L1h, *L1l, *L2h, *L2l, *H1h, *H1l;
    GSA(E, g_E); GSA(G, g_G); GSA(H2, g_H2);
    GSA(benc, g_benc); GSA(b2, g_b2); GSA(b1, g_b1);
    GSA(Yxh, g_Yxh); GSA(Yxl, g_Yxl);
    GSA(Weh, g_Wench); GSA(Wel, g_Wencl);
    GSA(W2h, g_W2h); GSA(W2l, g_W2l); GSA(W1h, g_W1h); GSA(W1l, g_W1l);
    GSA(x12h, g_x12h); GSA(x12l, g_x12l); GSA(xt1h, g_xt1h); GSA(xt1l, g_xt1l);
    GSA(L1h, g_L1h); GSA(L1l, g_L1l); GSA(L2h, g_L2h); GSA(L2l, g_L2l);
    GSA(H1h, g_H1h); GSA(H1l, g_H1l);

    const int SM = 81920;

    // launch order arranged so ncu (-s 5 -c 1) captures a gate GEMM (idx 5)
    pack_encN<<<(1920 * 64 + 255) / 256, 256>>>(in[1], in[3], in[5], in[7], in[9], in[11],
                                                in[2], in[4], in[6], in[8], in[10], in[12]);   // 0
    repack_yN<<<(NT * 64 + 255) / 256, 256>>>(in[0]);                                           // 1
    mma_gemm<0,3><<<dim3(15, PXT), 512, SM>>>(Yxh, Yxl, Weh, Wel, benc, E, 0, 0, 64, 2, 1, 0, SE, 0); // 2
    pack_recN<<<(1024 * 320 + 255) / 256, 256>>>(in[15], in[21], in[23], in[16], in[22], in[24], W2h, W2l, b2); // 3
    init_ew<<<NT, 320>>>();                                                                     // 4

    // it=0 stepA gates: d-tiles 0..2 at 3-term (idx 5, ncu target), f/i tiles 3..7 at 1-term
    mma_gemm<0,3><<<dim3(3, PXT), 512, SM>>>(x12h, x12l, W2h, W2l, b2, G, 0, 0, KR, 10, 1, 0, SG, 0); // 5
    mma_gemm<0,1><<<dim3(5, PXT), 512, SM>>>(x12h, x12l, W2h, W2l, b2, G, 0, 0, KR, 10, 1, 0, SG, 3); // 6
    pack_recN<<<(1024 * 320 + 255) / 256, 256>>>(in[13], in[17], in[19], in[14], in[18], in[20], W1h, W1l, b1); // 7
    stepA_ew<<<NT, 320>>>();                                                                    // 8

    for (int it = 0; it < 3; it++) {
        // stepB (gate '1')
        mma_gemm<0,3><<<dim3(3, PXT), 512, SM>>>(xt1h, xt1l, W1h, W1l, b1, G, 0, 0, KR, 10, 1, 0, SG, 0);
        mma_gemm<0,1><<<dim3(5, PXT), 512, SM>>>(xt1h, xt1l, W1h, W1l, b1, G, 0, 0, KR, 10, 1, 0, SG, 3);
        stepB_ew<<<NT, 320>>>();
        if (it < 2) {
            // next stepA (gate '2')
            mma_gemm<0,3><<<dim3(3, PXT), 512, SM>>>(x12h, x12l, W2h, W2l, b2, G, 0, 0, KR, 10, 1, 0, SG, 0);
            mma_gemm<0,1><<<dim3(5, PXT), 512, SM>>>(x12h, x12l, W2h, W2l, b2, G, 0, 0, KR, 10, 1, 0, SG, 3);
            stepA_ew<<<NT, 320>>>();
        }
    }
    // final stepA (4th application of gate '2')
    mma_gemm<0,3><<<dim3(3, PXT), 512, SM>>>(x12h, x12l, W2h, W2l, b2, G, 0, 0, KR, 10, 1, 0, SG, 0);
    mma_gemm<0,1><<<dim3(5, PXT), 512, SM>>>(x12h, x12l, W2h, W2l, b2, G, 0, 0, KR, 10, 1, 0, SG, 3);
    stepA_ew<<<NT, 320>>>();

    // head
    pack_l1N<<<(9 * 128 * 320 + 255) / 256, 256>>>(in[25]);
    pack_l2N<<<(128 * 128 + 255) / 256, 256>>>(in[27]);
    mma_gemm<1,3><<<dim3(1, PXT), 512, SM>>>(xt1h, xt1l, L1h, L1l, in[26], 0, H1h, H1l, KR, 10, 9, 1, 128, 0);
    mma_gemm<0,3><<<dim3(1, PXT), 512, SM>>>(H1h, H1l, L2h, L2l, in[28], H2, 0, 0, 128, 4, 1, 0, 128, 0);
    head_out<<<(NH + 255) / 256, 256>>>(in[29], in[30], (float*)d_out);
}